// round 10
// baseline (speedup 1.0000x reference)
#include <cuda_runtime.h>

#define NB 64
#define NM 1024
#define NK 16
#define NH 64
#define NN (NB*NM)
#define INF __int_as_float(0x7f800000)

typedef unsigned long long ull;

// tied-operand packed FMA: acc = a*b + acc, in place (no MOV pairs)
__device__ __forceinline__ void ffma2_acc(ull& c, ull a, ull b) {
    asm("fma.rn.f32x2 %0, %1, %2, %0;" : "+l"(c) : "l"(a), "l"(b));
}
__device__ __forceinline__ float lo32(ull v) { return __uint_as_float((unsigned)v); }
__device__ __forceinline__ float hi32(ull v) { return __uint_as_float((unsigned)(v >> 32)); }
__device__ __forceinline__ float sum2(ull v) { return lo32(v) + hi32(v); }
__device__ __forceinline__ ull pack2(float x, float y) {
    return (ull)__float_as_uint(x) | ((ull)__float_as_uint(y) << 32);
}

// ---------------- scratch (device globals; no allocations allowed) ----------
__device__ float g_h0[NN*NH];
__device__ float g_h1[NN*NH];
__device__ float g_sq[NN];
__device__ int   g_knn[NN*NK];

// ---------------- encoder: x[N,4] -> relu(relu(x@w1+b1)@w2+b2) -> g_h0, g_sq
__global__ __launch_bounds__(256) void k_encoder(
    const float* __restrict__ x,
    const float* __restrict__ w1, const float* __restrict__ b1,
    const float* __restrict__ w2, const float* __restrict__ b2)
{
    __shared__ float sw1[128], sb1[32], sw2[2048], sb2[64];
    int t = threadIdx.x;
    if (t < 128) sw1[t] = w1[t];
    if (t < 32)  sb1[t] = b1[t];
    if (t < 64)  sb2[t] = b2[t];
    for (int i = t; i < 2048; i += 256) sw2[i] = w2[i];
    __syncthreads();

    int node = blockIdx.x * 256 + t;
    float x0 = x[node*4+0], x1 = x[node*4+1], x2 = x[node*4+2], x3 = x[node*4+3];
    float hid[32];
    #pragma unroll
    for (int c = 0; c < 32; c++) {
        float a = sb1[c];
        a = fmaf(x0, sw1[c],      a);
        a = fmaf(x1, sw1[32+c],   a);
        a = fmaf(x2, sw1[64+c],   a);
        a = fmaf(x3, sw1[96+c],   a);
        hid[c] = fmaxf(a, 0.f);
    }
    float sq = 0.f;
    float* hrow = g_h0 + (size_t)node * NH;
    #pragma unroll 4
    for (int c4 = 0; c4 < 64; c4 += 4) {
        float a0 = sb2[c4], a1 = sb2[c4+1], a2 = sb2[c4+2], a3 = sb2[c4+3];
        #pragma unroll
        for (int k = 0; k < 32; k++) {
            float hv = hid[k];
            a0 = fmaf(hv, sw2[k*64+c4+0], a0);
            a1 = fmaf(hv, sw2[k*64+c4+1], a1);
            a2 = fmaf(hv, sw2[k*64+c4+2], a2);
            a3 = fmaf(hv, sw2[k*64+c4+3], a3);
        }
        a0 = fmaxf(a0,0.f); a1 = fmaxf(a1,0.f); a2 = fmaxf(a2,0.f); a3 = fmaxf(a3,0.f);
        *(float4*)(hrow + c4) = make_float4(a0,a1,a2,a3);
        sq = fmaf(a0,a0, fmaf(a1,a1, fmaf(a2,a2, fmaf(a3,a3, sq))));
    }
    g_sq[node] = sq;
}

// ---------------- kNN v6: conflict-free f32x2 GEMM (tied-FMA) + top-k scan
// grid (8, 64), 256 threads. Per block: 128 i-rows; j swept in 64-wide stripes.
// Thread tile: 4i x 8j with j scattered as {16q+2tj, 16q+2tj+1} so B loads are
// 16B-stride across lanes (conflict-free).
// smem bytes: hiP 32768 | hjP 16384 | D[128][68] 34816 | sqj 256 |
//             topd 8192 | topi 4096  = 96512 B
#define KNN_SMEM_BYTES 96512

__global__ __launch_bounds__(256, 2) void k_knn(int src)
{
    extern __shared__ char ksm[];
    ull*   hiP  = (ull*)ksm;                                // [32 k2][128 i]
    ull*   hjP  = (ull*)(ksm + 32768);                      // [32 k2][64 j]
    float* D    = (float*)(ksm + 49152);                    // [128][68]
    float* sqj  = (float*)(ksm + 83968);                    // [64]
    float* topd = (float*)(ksm + 84224);                    // [16][128]
    unsigned short* topi = (unsigned short*)(ksm + 92416);  // [16][128]

    const float* __restrict__ h = src ? g_h1 : g_h0;
    const int b = blockIdx.y;
    const int t = threadIdx.x;
    const int base = blockIdx.x * 128;
    const float* hb  = h + (size_t)b * NM * NH;
    const float* sqb = g_sq + b * NM;

    // ---- stage hiP once: i = idx&127 (lane-per-row), kc = idx>>7
    #pragma unroll
    for (int m = 0; m < 8; m++) {
        int idx = t + m * 256;
        int i = idx & 127, kc = idx >> 7;
        float4 v = ((const float4*)(hb + (size_t)(base + i) * NH))[kc];
        hiP[(2*kc  )*128 + i] = pack2(v.x, v.y);
        hiP[(2*kc+1)*128 + i] = pack2(v.z, v.w);
    }
    if (t < 128) {
        #pragma unroll
        for (int s = 0; s < 16; s++) topd[s*128 + t] = INF;
    }

    const int ti = t >> 3, tj = t & 7;
    const int i0 = ti * 4;
    const int selfrow = base + t;          // used by t<128 scan threads
    float cm = INF; int mp = 0;

    for (int j0 = 0; j0 < NM; j0 += 64) {
        __syncthreads();   // prior scan done (D, hjP free for reuse)
        #pragma unroll
        for (int m = 0; m < 4; m++) {
            int idx = t + m * 256;
            int j = idx & 63, kc = idx >> 6;
            float4 v = ((const float4*)(hb + (size_t)(j0 + j) * NH))[kc];
            hjP[(2*kc  )*64 + j] = pack2(v.x, v.y);
            hjP[(2*kc+1)*64 + j] = pack2(v.z, v.w);
        }
        if (t < 64) sqj[t] = sqb[j0 + t];
        __syncthreads();

        // ---- GEMM: acc[4i][8j], j index = 2q+bit -> column 16q+2tj+bit
        ull acc[4][8];
        #pragma unroll
        for (int i = 0; i < 4; i++)
            #pragma unroll
            for (int j = 0; j < 8; j++) acc[i][j] = 0ull;

        #pragma unroll 2
        for (int k2 = 0; k2 < 32; k2++) {
            ulonglong2 aA = *(const ulonglong2*)&hiP[k2*128 + i0];
            ulonglong2 aB = *(const ulonglong2*)&hiP[k2*128 + i0 + 2];
            ulonglong2 b0 = *(const ulonglong2*)&hjP[k2*64 +  0 + 2*tj];
            ulonglong2 b1 = *(const ulonglong2*)&hjP[k2*64 + 16 + 2*tj];
            ulonglong2 b2 = *(const ulonglong2*)&hjP[k2*64 + 32 + 2*tj];
            ulonglong2 b3 = *(const ulonglong2*)&hjP[k2*64 + 48 + 2*tj];
            ull av[4] = {aA.x, aA.y, aB.x, aB.y};
            ull bv[8] = {b0.x, b0.y, b1.x, b1.y, b2.x, b2.y, b3.x, b3.y};
            #pragma unroll
            for (int i = 0; i < 4; i++)
                #pragma unroll
                for (int j = 0; j < 8; j++)
                    ffma2_acc(acc[i][j], av[i], bv[j]);
        }

        // ---- epilogue: keys -> D at owned columns (float2 stores)
        #pragma unroll
        for (int q = 0; q < 4; q++) {
            float2 sjq = *(const float2*)&sqj[16*q + 2*tj];
            #pragma unroll
            for (int i = 0; i < 4; i++) {
                float v0 = fmaf(-2.f, sum2(acc[i][2*q  ]), sjq.x);
                float v1 = fmaf(-2.f, sum2(acc[i][2*q+1]), sjq.y);
                *(float2*)&D[(i0+i)*68 + 16*q + 2*tj] = make_float2(v0, v1);
            }
        }
        __syncthreads();

        // ---- scan: one thread per i-row, threshold-heap insert
        if (t < 128) {
            #pragma unroll 4
            for (int q = 0; q < 16; q++) {
                float4 dv = *(const float4*)&D[t*68 + q*4];
                float kv[4] = {dv.x, dv.y, dv.z, dv.w};
                #pragma unroll
                for (int l = 0; l < 4; l++) {
                    int j = j0 + q*4 + l;
                    float key = kv[l];
                    if (key < cm && j != selfrow) {
                        topd[mp*128 + t] = key;
                        topi[mp*128 + t] = (unsigned short)j;
                        cm = -INF;
                        #pragma unroll
                        for (int s = 0; s < 16; s++) {
                            float v = topd[s*128 + t];
                            if (v > cm) { cm = v; mp = s; }
                        }
                    }
                }
            }
        }
    }
    __syncthreads();
    if (t < 128) {
        int* out = g_knn + (size_t)(b*NM + base + t) * NK;
        #pragma unroll
        for (int s = 0; s < 16; s++) out[s] = b*NM + (int)topi[s*128 + t];
    }
}

// ---------------- EdgeConv v4: persistent blocks, tied-FMA mainloops
// 8 nodes (128 edges) per tile, 256 threads, 4 edges x 8 channels per thread.
#define EC_SMEM_BYTES (21760 * 4)
#define EC_GRID 296
#define NTILES (NN/8)

__global__ __launch_bounds__(256, 2) void k_edgeconv(
    int src,
    const float* __restrict__ w1, const float* __restrict__ b1,
    const float* __restrict__ w2, const float* __restrict__ b2)
{
    extern __shared__ float sm[];
    float* w1x   = sm;                 // [k][c], k<64 (untransposed)
    float* w1Td  = sm + 4096;          // [cout][kin] swizzled
    float* w2T   = sm + 8192;          // [cout][cin] swizzled
    float* DH    = sm + 12288;         // [e][k] swizzled; reused as Hrow
    float* his   = sm + 20480;         // [8][64]
    float* bnode = sm + 20992;         // [8][64]
    float* b1s   = sm + 21504;
    float* b2s   = sm + 21568;
    int*   jid   = (int*)(sm + 21632);

    const float* hin  = src ? g_h1 : g_h0;
    float*       hout = src ? g_h0 : g_h1;

    const int t = threadIdx.x;

    // -------- stage weights ONCE (transposed + XOR-swizzled)
    for (int i = t; i < 4096; i += 256) w1x[i] = w1[i];
    for (int i = t; i < 4096; i += 256) {
        int c = i & 63, k = i >> 6;
        w1Td[c*64 + ((((k>>2) ^ (c>>3)) & 15) << 2) + (k & 3)] = w1[(64+k)*64 + c];
    }
    for (int i = t; i < 4096; i += 256) {
        int c = i & 63, k = i >> 6;
        w2T[c*64 + ((((k>>2) ^ (c>>3)) & 15) << 2) + (k & 3)] = w2[k*64 + c];
    }
    if (t < 64) { b1s[t] = b1[t]; b2s[t] = b2[t]; }

    const int cg = t & 7, eg = t >> 3;
    const int e0 = eg << 2, cb = cg << 3;
    const int n  = eg >> 2;
    const int esw = eg & 3;

    for (int tile = blockIdx.x; tile < NTILES; tile += EC_GRID) {
        int node0 = tile * 8;
        __syncthreads();   // previous tile fully done with his/jid/DH

        if (t < 128) ((float4*)his)[t] = ((const float4*)(hin + (size_t)node0 * NH))[t];
        else         jid[t-128] = g_knn[node0*NK + (t-128)];
        __syncthreads();

        // -------- phase 1: DH = (x_j - x_i) k-major swizzled; bnode = x_i@W1x + b1
        if (t >= 128) {
            int e = t - 128;
            int nn = e >> 4;
            const float4* hj4 = (const float4*)(hin + (size_t)jid[e] * NH);
            const float4* hi4 = (const float4*)(his + nn * NH);
            int ebase = e * 64, es = (e >> 2) & 3;
            #pragma unroll
            for (int f = 0; f < 16; f++) {
                float4 a = hj4[f]; float4 c = hi4[f];
                *(float4*)&DH[ebase + ((f ^ es) << 2)] =
                    make_float4(a.x - c.x, a.y - c.y, a.z - c.z, a.w - c.w);
            }
        } else {
            int nn = t >> 4, c0 = (t & 15) << 2;
            float a0 = b1s[c0], a1 = b1s[c0+1], a2 = b1s[c0+2], a3 = b1s[c0+3];
            #pragma unroll 4
            for (int k4 = 0; k4 < 16; k4++) {
                float4 av = *(const float4*)&his[nn*64 + 4*k4];
                float aa[4] = {av.x, av.y, av.z, av.w};
                #pragma unroll
                for (int kk = 0; kk < 4; kk++) {
                    float4 wv = *(const float4*)&w1x[(4*k4+kk)*64 + c0];
                    a0 = fmaf(aa[kk], wv.x, a0);
                    a1 = fmaf(aa[kk], wv.y, a1);
                    a2 = fmaf(aa[kk], wv.z, a2);
                    a3 = fmaf(aa[kk], wv.w, a3);
                }
            }
            *(float4*)&bnode[nn*64 + c0] = make_float4(a0, a1, a2, a3);
        }
        __syncthreads();

        // -------- layer 1 (diff half), f32x2 packed along kin (tied FMA)
        ull acc[4][8];
        #pragma unroll
        for (int i = 0; i < 4; i++)
            #pragma unroll
            for (int j = 0; j < 8; j++) acc[i][j] = 0ull;

        #pragma unroll 2
        for (int k4 = 0; k4 < 16; k4++) {
            int sa = (k4 ^ esw) << 2;
            ulonglong2 av[4];
            #pragma unroll
            for (int i = 0; i < 4; i++)
                av[i] = *(const ulonglong2*)&DH[(e0+i)*64 + sa];
            int sw = (k4 ^ cg) << 2;
            #pragma unroll
            for (int j = 0; j < 8; j++) {
                ulonglong2 wv = *(const ulonglong2*)&w1Td[(cb+j)*64 + sw];
                #pragma unroll
                for (int i = 0; i < 4; i++) {
                    ffma2_acc(acc[i][j], av[i].x, wv.x);
                    ffma2_acc(acc[i][j], av[i].y, wv.y);
                }
            }
        }
        __syncthreads();   // all DH reads complete

        // relu(bnode + diff) -> Hrow (aliases DH), k-major swizzled
        {
            float4 bn0 = *(const float4*)&bnode[n*64 + cb];
            float4 bn1 = *(const float4*)&bnode[n*64 + cb + 4];
            float bb[8] = {bn0.x,bn0.y,bn0.z,bn0.w, bn1.x,bn1.y,bn1.z,bn1.w};
            int s0 = ((cb>>2) ^ esw) << 2;
            int s1 = (((cb>>2)+1) ^ esw) << 2;
            #pragma unroll
            for (int i = 0; i < 4; i++) {
                int e = e0 + i;
                float h0 = fmaxf(bb[0] + sum2(acc[i][0]), 0.f);
                float h1 = fmaxf(bb[1] + sum2(acc[i][1]), 0.f);
                float h2 = fmaxf(bb[2] + sum2(acc[i][2]), 0.f);
                float h3 = fmaxf(bb[3] + sum2(acc[i][3]), 0.f);
                float h4 = fmaxf(bb[4] + sum2(acc[i][4]), 0.f);
                float h5 = fmaxf(bb[5] + sum2(acc[i][5]), 0.f);
                float h6 = fmaxf(bb[6] + sum2(acc[i][6]), 0.f);
                float h7 = fmaxf(bb[7] + sum2(acc[i][7]), 0.f);
                *(float4*)&DH[e*64 + s0] = make_float4(h0, h1, h2, h3);
                *(float4*)&DH[e*64 + s1] = make_float4(h4, h5, h6, h7);
            }
        }
        __syncthreads();

        // -------- layer 2, f32x2 packed along cin (tied FMA)
        ull acc2[4][8];
        #pragma unroll
        for (int i = 0; i < 4; i++)
            #pragma unroll
            for (int j = 0; j < 8; j++) acc2[i][j] = 0ull;

        #pragma unroll 2
        for (int k4 = 0; k4 < 16; k4++) {
            int sa = (k4 ^ esw) << 2;
            ulonglong2 av[4];
            #pragma unroll
            for (int i = 0; i < 4; i++)
                av[i] = *(const ulonglong2*)&DH[(e0+i)*64 + sa];
            int sw = (k4 ^ cg) << 2;
            #pragma unroll
            for (int j = 0; j < 8; j++) {
                ulonglong2 wv = *(const ulonglong2*)&w2T[(cb+j)*64 + sw];
                #pragma unroll
                for (int i = 0; i < 4; i++) {
                    ffma2_acc(acc2[i][j], av[i].x, wv.x);
                    ffma2_acc(acc2[i][j], av[i].y, wv.y);
                }
            }
        }

        // -------- epilogue: +b2, max over 4 edges, shfl-max over edge groups
        float m[8];
        #pragma unroll
        for (int j = 0; j < 8; j++) {
            float bj = b2s[cb + j];
            float v0 = bj + sum2(acc2[0][j]);
            float v1 = bj + sum2(acc2[1][j]);
            float v2 = bj + sum2(acc2[2][j]);
            float v3 = bj + sum2(acc2[3][j]);
            m[j] = fmaxf(fmaxf(v0, v1), fmaxf(v2, v3));
        }
        #pragma unroll
        for (int j = 0; j < 8; j++) {
            m[j] = fmaxf(m[j], __shfl_xor_sync(0xffffffffu, m[j], 8));
            m[j] = fmaxf(m[j], __shfl_xor_sync(0xffffffffu, m[j], 16));
        }
        if (esw == 0) {
            float* orow = hout + (size_t)(node0 + n) * NH + cb;
            *(float4*)orow     = make_float4(m[0], m[1], m[2], m[3]);
            *(float4*)(orow+4) = make_float4(m[4], m[5], m[6], m[7]);
        }
        float s2 = 0.f;
        #pragma unroll
        for (int j = 0; j < 8; j++) s2 = fmaf(m[j], m[j], s2);
        s2 += __shfl_xor_sync(0xffffffffu, s2, 1);
        s2 += __shfl_xor_sync(0xffffffffu, s2, 2);
        s2 += __shfl_xor_sync(0xffffffffu, s2, 4);
        if ((t & 31) == 0) g_sq[node0 + n] = s2;
    }
}

// ---------------- mean pool + output MLP -> d_out[64]
__global__ __launch_bounds__(256) void k_final(
    const float* __restrict__ w1, const float* __restrict__ b1,
    const float* __restrict__ w2, const float* __restrict__ b2,
    float* __restrict__ out)
{
    int b = blockIdx.x, t = threadIdx.x;
    const float* hb = g_h0 + (size_t)b * NM * NH;   // edgeconv2 wrote g_h0
    __shared__ float red[256];
    __shared__ float g[64];
    __shared__ float hid[32];

    int c = t & 63, r0 = t >> 6;
    float acc = 0.f;
    for (int m = r0; m < NM; m += 4) acc += hb[(size_t)m * NH + c];
    red[t] = acc;
    __syncthreads();
    if (t < 64)
        g[t] = (red[t] + red[t+64] + red[t+128] + red[t+192]) * (1.f/1024.f);
    __syncthreads();
    if (t < 32) {
        float a = b1[t];
        #pragma unroll 8
        for (int k = 0; k < 64; k++) a = fmaf(g[k], w1[k*32 + t], a);
        hid[t] = fmaxf(a, 0.f);
    }
    __syncthreads();
    if (t < 32) {
        float v = hid[t] * w2[t];
        #pragma unroll
        for (int off = 16; off > 0; off >>= 1)
            v += __shfl_down_sync(0xffffffffu, v, off);
        if (t == 0) out[b] = v + b2[0];
    }
}

// ---------------- launch ----------------------------------------------------
extern "C" void kernel_launch(void* const* d_in, const int* in_sizes, int n_in,
                              void* d_out, int out_size)
{
    const float* x      = (const float*)d_in[0];
    // d_in[1] = batch (int64) — equal-size graphs, unused
    const float* enc_w1 = (const float*)d_in[2];
    const float* enc_b1 = (const float*)d_in[3];
    const float* enc_w2 = (const float*)d_in[4];
    const float* enc_b2 = (const float*)d_in[5];
    const float* ec1_w1 = (const float*)d_in[6];
    const float* ec1_b1 = (const float*)d_in[7];
    const float* ec1_w2 = (const float*)d_in[8];
    const float* ec1_b2 = (const float*)d_in[9];
    const float* ec2_w1 = (const float*)d_in[10];
    const float* ec2_b1 = (const float*)d_in[11];
    const float* ec2_w2 = (const float*)d_in[12];
    const float* ec2_b2 = (const float*)d_in[13];
    const float* out_w1 = (const float*)d_in[14];
    const float* out_b1 = (const float*)d_in[15];
    const float* out_w2 = (const float*)d_in[16];
    const float* out_b2 = (const float*)d_in[17];
    float* out = (float*)d_out;

    cudaFuncSetAttribute(k_edgeconv, cudaFuncAttributeMaxDynamicSharedMemorySize,
                         EC_SMEM_BYTES);
    cudaFuncSetAttribute(k_knn, cudaFuncAttributeMaxDynamicSharedMemorySize,
                         KNN_SMEM_BYTES);

    k_encoder<<<NN/256, 256>>>(x, enc_w1, enc_b1, enc_w2, enc_b2);
    k_knn<<<dim3(NM/128, NB), 256, KNN_SMEM_BYTES>>>(0);
    k_edgeconv<<<EC_GRID, 256, EC_SMEM_BYTES>>>(0, ec1_w1, ec1_b1, ec1_w2, ec1_b2);
    k_knn<<<dim3(NM/128, NB), 256, KNN_SMEM_BYTES>>>(1);
    k_edgeconv<<<EC_GRID, 256, EC_SMEM_BYTES>>>(1, ec2_w1, ec2_b1, ec2_w2, ec2_b2);
    k_final<<<NB, 256>>>(out_w1, out_b1, out_w2, out_b2, out);
}

// round 15
// speedup vs baseline: 1.0085x; 1.0085x over previous
#include <cuda_runtime.h>

#define NB 64
#define NM 1024
#define NK 16
#define NH 64
#define NN (NB*NM)
#define INF __int_as_float(0x7f800000)

typedef unsigned long long ull;

__device__ __forceinline__ void ffma2_acc(ull& c, ull a, ull b) {
    asm("fma.rn.f32x2 %0, %1, %2, %0;" : "+l"(c) : "l"(a), "l"(b));
}
__device__ __forceinline__ float lo32(ull v) { return __uint_as_float((unsigned)v); }
__device__ __forceinline__ float hi32(ull v) { return __uint_as_float((unsigned)(v >> 32)); }
__device__ __forceinline__ float sum2(ull v) { return lo32(v) + hi32(v); }
__device__ __forceinline__ ull pack2(float x, float y) {
    return (ull)__float_as_uint(x) | ((ull)__float_as_uint(y) << 32);
}

// ---------------- scratch (device globals; no allocations allowed) ----------
__device__ float g_h0[NN*NH];
__device__ float g_h1[NN*NH];
__device__ float g_sq[NN];
__device__ int   g_knn[NN*NK];

// ---------------- encoder: x[N,4] -> relu(relu(x@w1+b1)@w2+b2) -> g_h0, g_sq
__global__ __launch_bounds__(256) void k_encoder(
    const float* __restrict__ x,
    const float* __restrict__ w1, const float* __restrict__ b1,
    const float* __restrict__ w2, const float* __restrict__ b2)
{
    __shared__ float sw1[128], sb1[32], sw2[2048], sb2[64];
    int t = threadIdx.x;
    if (t < 128) sw1[t] = w1[t];
    if (t < 32)  sb1[t] = b1[t];
    if (t < 64)  sb2[t] = b2[t];
    for (int i = t; i < 2048; i += 256) sw2[i] = w2[i];
    __syncthreads();

    int node = blockIdx.x * 256 + t;
    float x0 = x[node*4+0], x1 = x[node*4+1], x2 = x[node*4+2], x3 = x[node*4+3];
    float hid[32];
    #pragma unroll
    for (int c = 0; c < 32; c++) {
        float a = sb1[c];
        a = fmaf(x0, sw1[c],      a);
        a = fmaf(x1, sw1[32+c],   a);
        a = fmaf(x2, sw1[64+c],   a);
        a = fmaf(x3, sw1[96+c],   a);
        hid[c] = fmaxf(a, 0.f);
    }
    float sq = 0.f;
    float* hrow = g_h0 + (size_t)node * NH;
    #pragma unroll 4
    for (int c4 = 0; c4 < 64; c4 += 4) {
        float a0 = sb2[c4], a1 = sb2[c4+1], a2 = sb2[c4+2], a3 = sb2[c4+3];
        #pragma unroll
        for (int k = 0; k < 32; k++) {
            float hv = hid[k];
            a0 = fmaf(hv, sw2[k*64+c4+0], a0);
            a1 = fmaf(hv, sw2[k*64+c4+1], a1);
            a2 = fmaf(hv, sw2[k*64+c4+2], a2);
            a3 = fmaf(hv, sw2[k*64+c4+3], a3);
        }
        a0 = fmaxf(a0,0.f); a1 = fmaxf(a1,0.f); a2 = fmaxf(a2,0.f); a3 = fmaxf(a3,0.f);
        *(float4*)(hrow + c4) = make_float4(a0,a1,a2,a3);
        sq = fmaf(a0,a0, fmaf(a1,a1, fmaf(a2,a2, fmaf(a3,a3, sq))));
    }
    g_sq[node] = sq;
}

// ---------------- kNN v7: 128 threads, 8i x 8j register tiles, f32x2 GEMM
// grid (8, 64), 128 threads. Per block: 128 i-rows; j swept in 64-wide stripes.
// tg = t>>3 (16 groups of 8 i-rows), tj = t&7; j owned = {16q+2tj, 16q+2tj+1}.
// 2 blocks/SM -> 256 thr/SM -> 255-reg budget: ptxas can pipeline the loads.
// smem bytes: hiP 32768 | hjP 16384 | D[128][68] 34816 | sqj 256 |
//             topd 8192 | topi 4096  = 96512 B
#define KNN_SMEM_BYTES 96512

__global__ __launch_bounds__(128, 2) void k_knn(int src)
{
    extern __shared__ char ksm[];
    ull*   hiP  = (ull*)ksm;                                // [32 k2][128 i]
    ull*   hjP  = (ull*)(ksm + 32768);                      // [32 k2][64 j]
    float* D    = (float*)(ksm + 49152);                    // [128][68]
    float* sqj  = (float*)(ksm + 83968);                    // [64]
    float* topd = (float*)(ksm + 84224);                    // [16][128]
    unsigned short* topi = (unsigned short*)(ksm + 92416);  // [16][128]

    const float* __restrict__ h = src ? g_h1 : g_h0;
    const int b = blockIdx.y;
    const int t = threadIdx.x;
    const int base = blockIdx.x * 128;
    const float* hb  = h + (size_t)b * NM * NH;
    const float* sqb = g_sq + b * NM;

    // ---- stage hiP once (128 rows x 16 float4)
    #pragma unroll
    for (int m = 0; m < 16; m++) {
        int idx = t + m * 128;
        int i = idx & 127, kc = idx >> 7;
        float4 v = ((const float4*)(hb + (size_t)(base + i) * NH))[kc];
        hiP[(2*kc  )*128 + i] = pack2(v.x, v.y);
        hiP[(2*kc+1)*128 + i] = pack2(v.z, v.w);
    }
    #pragma unroll
    for (int s = 0; s < 16; s++) topd[s*128 + t] = INF;

    const ulonglong2* hiP2 = (const ulonglong2*)hiP;   // row = 64 ulonglong2
    const ulonglong2* hjP2 = (const ulonglong2*)hjP;   // row = 32 ulonglong2
    const int tg = t >> 3, tj = t & 7;
    const int i0 = tg * 8;
    const int selfrow = base + t;
    float cm = INF; int mp = 0;

    for (int j0 = 0; j0 < NM; j0 += 64) {
        __syncthreads();   // prior scan done (D, hjP free for reuse)
        #pragma unroll
        for (int m = 0; m < 8; m++) {
            int idx = t + m * 128;
            int j = idx & 63, kc = idx >> 6;
            float4 v = ((const float4*)(hb + (size_t)(j0 + j) * NH))[kc];
            hjP[(2*kc  )*64 + j] = pack2(v.x, v.y);
            hjP[(2*kc+1)*64 + j] = pack2(v.z, v.w);
        }
        if (t < 64) sqj[t] = sqb[j0 + t];
        __syncthreads();

        // ---- GEMM: acc[8i][8j], tied f32x2 FMAs
        ull acc[8][8];
        #pragma unroll
        for (int i = 0; i < 8; i++)
            #pragma unroll
            for (int j = 0; j < 8; j++) acc[i][j] = 0ull;

        #pragma unroll 2
        for (int k2 = 0; k2 < 32; k2++) {
            ulonglong2 A0 = hiP2[k2*64 + tg*4 + 0];
            ulonglong2 A1 = hiP2[k2*64 + tg*4 + 1];
            ulonglong2 A2 = hiP2[k2*64 + tg*4 + 2];
            ulonglong2 A3 = hiP2[k2*64 + tg*4 + 3];
            ulonglong2 B0 = hjP2[k2*32 +  0 + tj];
            ulonglong2 B1 = hjP2[k2*32 +  8 + tj];
            ulonglong2 B2 = hjP2[k2*32 + 16 + tj];
            ulonglong2 B3 = hjP2[k2*32 + 24 + tj];
            ull av[8] = {A0.x, A0.y, A1.x, A1.y, A2.x, A2.y, A3.x, A3.y};
            ull bv[8] = {B0.x, B0.y, B1.x, B1.y, B2.x, B2.y, B3.x, B3.y};
            #pragma unroll
            for (int i = 0; i < 8; i++)
                #pragma unroll
                for (int j = 0; j < 8; j++)
                    ffma2_acc(acc[i][j], av[i], bv[j]);
        }

        // ---- epilogue: keys -> D at owned columns (float2 stores)
        #pragma unroll
        for (int q = 0; q < 4; q++) {
            float2 sjq = *(const float2*)&sqj[16*q + 2*tj];
            #pragma unroll
            for (int i = 0; i < 8; i++) {
                float v0 = fmaf(-2.f, sum2(acc[i][2*q  ]), sjq.x);
                float v1 = fmaf(-2.f, sum2(acc[i][2*q+1]), sjq.y);
                *(float2*)&D[(i0+i)*68 + 16*q + 2*tj] = make_float2(v0, v1);
            }
        }
        __syncthreads();

        // ---- scan: every thread owns one i-row, threshold-heap insert
        #pragma unroll 4
        for (int q = 0; q < 16; q++) {
            float4 dv = *(const float4*)&D[t*68 + q*4];
            float kv[4] = {dv.x, dv.y, dv.z, dv.w};
            #pragma unroll
            for (int l = 0; l < 4; l++) {
                int j = j0 + q*4 + l;
                float key = kv[l];
                if (key < cm && j != selfrow) {
                    topd[mp*128 + t] = key;
                    topi[mp*128 + t] = (unsigned short)j;
                    cm = -INF;
                    #pragma unroll
                    for (int s = 0; s < 16; s++) {
                        float v = topd[s*128 + t];
                        if (v > cm) { cm = v; mp = s; }
                    }
                }
            }
        }
    }
    __syncthreads();
    {
        int* out = g_knn + (size_t)(b*NM + base + t) * NK;
        #pragma unroll
        for (int s = 0; s < 16; s++) out[s] = b*NM + (int)topi[s*128 + t];
    }
}

// ---------------- EdgeConv v4: persistent blocks, tied-FMA mainloops
// 8 nodes (128 edges) per tile, 256 threads, 4 edges x 8 channels per thread.
#define EC_SMEM_BYTES (21760 * 4)
#define EC_GRID 296
#define NTILES (NN/8)

__global__ __launch_bounds__(256, 2) void k_edgeconv(
    int src,
    const float* __restrict__ w1, const float* __restrict__ b1,
    const float* __restrict__ w2, const float* __restrict__ b2)
{
    extern __shared__ float sm[];
    float* w1x   = sm;                 // [k][c], k<64 (untransposed)
    float* w1Td  = sm + 4096;          // [cout][kin] swizzled
    float* w2T   = sm + 8192;          // [cout][cin] swizzled
    float* DH    = sm + 12288;         // [e][k] swizzled; reused as Hrow
    float* his   = sm + 20480;         // [8][64]
    float* bnode = sm + 20992;         // [8][64]
    float* b1s   = sm + 21504;
    float* b2s   = sm + 21568;
    int*   jid   = (int*)(sm + 21632);

    const float* hin  = src ? g_h1 : g_h0;
    float*       hout = src ? g_h0 : g_h1;

    const int t = threadIdx.x;

    // -------- stage weights ONCE (transposed + XOR-swizzled)
    for (int i = t; i < 4096; i += 256) w1x[i] = w1[i];
    for (int i = t; i < 4096; i += 256) {
        int c = i & 63, k = i >> 6;
        w1Td[c*64 + ((((k>>2) ^ (c>>3)) & 15) << 2) + (k & 3)] = w1[(64+k)*64 + c];
    }
    for (int i = t; i < 4096; i += 256) {
        int c = i & 63, k = i >> 6;
        w2T[c*64 + ((((k>>2) ^ (c>>3)) & 15) << 2) + (k & 3)] = w2[k*64 + c];
    }
    if (t < 64) { b1s[t] = b1[t]; b2s[t] = b2[t]; }

    const int cg = t & 7, eg = t >> 3;
    const int e0 = eg << 2, cb = cg << 3;
    const int n  = eg >> 2;
    const int esw = eg & 3;

    for (int tile = blockIdx.x; tile < NTILES; tile += EC_GRID) {
        int node0 = tile * 8;
        __syncthreads();   // previous tile fully done with his/jid/DH

        if (t < 128) ((float4*)his)[t] = ((const float4*)(hin + (size_t)node0 * NH))[t];
        else         jid[t-128] = g_knn[node0*NK + (t-128)];
        __syncthreads();

        // -------- phase 1: DH = (x_j - x_i) k-major swizzled; bnode = x_i@W1x + b1
        if (t >= 128) {
            int e = t - 128;
            int nn = e >> 4;
            const float4* hj4 = (const float4*)(hin + (size_t)jid[e] * NH);
            const float4* hi4 = (const float4*)(his + nn * NH);
            int ebase = e * 64, es = (e >> 2) & 3;
            #pragma unroll
            for (int f = 0; f < 16; f++) {
                float4 a = hj4[f]; float4 c = hi4[f];
                *(float4*)&DH[ebase + ((f ^ es) << 2)] =
                    make_float4(a.x - c.x, a.y - c.y, a.z - c.z, a.w - c.w);
            }
        } else {
            int nn = t >> 4, c0 = (t & 15) << 2;
            float a0 = b1s[c0], a1 = b1s[c0+1], a2 = b1s[c0+2], a3 = b1s[c0+3];
            #pragma unroll 4
            for (int k4 = 0; k4 < 16; k4++) {
                float4 av = *(const float4*)&his[nn*64 + 4*k4];
                float aa[4] = {av.x, av.y, av.z, av.w};
                #pragma unroll
                for (int kk = 0; kk < 4; kk++) {
                    float4 wv = *(const float4*)&w1x[(4*k4+kk)*64 + c0];
                    a0 = fmaf(aa[kk], wv.x, a0);
                    a1 = fmaf(aa[kk], wv.y, a1);
                    a2 = fmaf(aa[kk], wv.z, a2);
                    a3 = fmaf(aa[kk], wv.w, a3);
                }
            }
            *(float4*)&bnode[nn*64 + c0] = make_float4(a0, a1, a2, a3);
        }
        __syncthreads();

        // -------- layer 1 (diff half), f32x2 packed along kin (tied FMA)
        ull acc[4][8];
        #pragma unroll
        for (int i = 0; i < 4; i++)
            #pragma unroll
            for (int j = 0; j < 8; j++) acc[i][j] = 0ull;

        #pragma unroll 2
        for (int k4 = 0; k4 < 16; k4++) {
            int sa = (k4 ^ esw) << 2;
            ulonglong2 av[4];
            #pragma unroll
            for (int i = 0; i < 4; i++)
                av[i] = *(const ulonglong2*)&DH[(e0+i)*64 + sa];
            int sw = (k4 ^ cg) << 2;
            #pragma unroll
            for (int j = 0; j < 8; j++) {
                ulonglong2 wv = *(const ulonglong2*)&w1Td[(cb+j)*64 + sw];
                #pragma unroll
                for (int i = 0; i < 4; i++) {
                    ffma2_acc(acc[i][j], av[i].x, wv.x);
                    ffma2_acc(acc[i][j], av[i].y, wv.y);
                }
            }
        }
        __syncthreads();   // all DH reads complete

        // relu(bnode + diff) -> Hrow (aliases DH), k-major swizzled
        {
            float4 bn0 = *(const float4*)&bnode[n*64 + cb];
            float4 bn1 = *(const float4*)&bnode[n*64 + cb + 4];
            float bb[8] = {bn0.x,bn0.y,bn0.z,bn0.w, bn1.x,bn1.y,bn1.z,bn1.w};
            int s0 = ((cb>>2) ^ esw) << 2;
            int s1 = (((cb>>2)+1) ^ esw) << 2;
            #pragma unroll
            for (int i = 0; i < 4; i++) {
                int e = e0 + i;
                float h0 = fmaxf(bb[0] + sum2(acc[i][0]), 0.f);
                float h1 = fmaxf(bb[1] + sum2(acc[i][1]), 0.f);
                float h2 = fmaxf(bb[2] + sum2(acc[i][2]), 0.f);
                float h3 = fmaxf(bb[3] + sum2(acc[i][3]), 0.f);
                float h4 = fmaxf(bb[4] + sum2(acc[i][4]), 0.f);
                float h5 = fmaxf(bb[5] + sum2(acc[i][5]), 0.f);
                float h6 = fmaxf(bb[6] + sum2(acc[i][6]), 0.f);
                float h7 = fmaxf(bb[7] + sum2(acc[i][7]), 0.f);
                *(float4*)&DH[e*64 + s0] = make_float4(h0, h1, h2, h3);
                *(float4*)&DH[e*64 + s1] = make_float4(h4, h5, h6, h7);
            }
        }
        __syncthreads();

        // -------- layer 2, f32x2 packed along cin (tied FMA)
        ull acc2[4][8];
        #pragma unroll
        for (int i = 0; i < 4; i++)
            #pragma unroll
            for (int j = 0; j < 8; j++) acc2[i][j] = 0ull;

        #pragma unroll 2
        for (int k4 = 0; k4 < 16; k4++) {
            int sa = (k4 ^ esw) << 2;
            ulonglong2 av[4];
            #pragma unroll
            for (int i = 0; i < 4; i++)
                av[i] = *(const ulonglong2*)&DH[(e0+i)*64 + sa];
            int sw = (k4 ^ cg) << 2;
            #pragma unroll
            for (int j = 0; j < 8; j++) {
                ulonglong2 wv = *(const ulonglong2*)&w2T[(cb+j)*64 + sw];
                #pragma unroll
                for (int i = 0; i < 4; i++) {
                    ffma2_acc(acc2[i][j], av[i].x, wv.x);
                    ffma2_acc(acc2[i][j], av[i].y, wv.y);
                }
            }
        }

        // -------- epilogue: +b2, max over 4 edges, shfl-max over edge groups
        float m[8];
        #pragma unroll
        for (int j = 0; j < 8; j++) {
            float bj = b2s[cb + j];
            float v0 = bj + sum2(acc2[0][j]);
            float v1 = bj + sum2(acc2[1][j]);
            float v2 = bj + sum2(acc2[2][j]);
            float v3 = bj + sum2(acc2[3][j]);
            m[j] = fmaxf(fmaxf(v0, v1), fmaxf(v2, v3));
        }
        #pragma unroll
        for (int j = 0; j < 8; j++) {
            m[j] = fmaxf(m[j], __shfl_xor_sync(0xffffffffu, m[j], 8));
            m[j] = fmaxf(m[j], __shfl_xor_sync(0xffffffffu, m[j], 16));
        }
        if (esw == 0) {
            float* orow = hout + (size_t)(node0 + n) * NH + cb;
            *(float4*)orow     = make_float4(m[0], m[1], m[2], m[3]);
            *(float4*)(orow+4) = make_float4(m[4], m[5], m[6], m[7]);
        }
        float s2 = 0.f;
        #pragma unroll
        for (int j = 0; j < 8; j++) s2 = fmaf(m[j], m[j], s2);
        s2 += __shfl_xor_sync(0xffffffffu, s2, 1);
        s2 += __shfl_xor_sync(0xffffffffu, s2, 2);
        s2 += __shfl_xor_sync(0xffffffffu, s2, 4);
        if ((t & 31) == 0) g_sq[node0 + n] = s2;
    }
}

// ---------------- mean pool + output MLP -> d_out[64]
__global__ __launch_bounds__(256) void k_final(
    const float* __restrict__ w1, const float* __restrict__ b1,
    const float* __restrict__ w2, const float* __restrict__ b2,
    float* __restrict__ out)
{
    int b = blockIdx.x, t = threadIdx.x;
    const float* hb = g_h0 + (size_t)b * NM * NH;   // edgeconv2 wrote g_h0
    __shared__ float red[256];
    __shared__ float g[64];
    __shared__ float hid[32];

    int c = t & 63, r0 = t >> 6;
    float acc = 0.f;
    for (int m = r0; m < NM; m += 4) acc += hb[(size_t)m * NH + c];
    red[t] = acc;
    __syncthreads();
    if (t < 64)
        g[t] = (red[t] + red[t+64] + red[t+128] + red[t+192]) * (1.f/1024.f);
    __syncthreads();
    if (t < 32) {
        float a = b1[t];
        #pragma unroll 8
        for (int k = 0; k < 64; k++) a = fmaf(g[k], w1[k*32 + t], a);
        hid[t] = fmaxf(a, 0.f);
    }
    __syncthreads();
    if (t < 32) {
        float v = hid[t] * w2[t];
        #pragma unroll
        for (int off = 16; off > 0; off >>= 1)
            v += __shfl_down_sync(0xffffffffu, v, off);
        if (t == 0) out[b] = v + b2[0];
    }
}

// ---------------- launch ----------------------------------------------------
extern "C" void kernel_launch(void* const* d_in, const int* in_sizes, int n_in,
                              void* d_out, int out_size)
{
    const float* x      = (const float*)d_in[0];
    // d_in[1] = batch (int64) — equal-size graphs, unused
    const float* enc_w1 = (const float*)d_in[2];
    const float* enc_b1 = (const float*)d_in[3];
    const float* enc_w2 = (const float*)d_in[4];
    const float* enc_b2 = (const float*)d_in[5];
    const float* ec1_w1 = (const float*)d_in[6];
    const float* ec1_b1 = (const float*)d_in[7];
    const float* ec1_w2 = (const float*)d_in[8];
    const float* ec1_b2 = (const float*)d_in[9];
    const float* ec2_w1 = (const float*)d_in[10];
    const float* ec2_b1 = (const float*)d_in[11];
    const float* ec2_w2 = (const float*)d_in[12];
    const float* ec2_b2 = (const float*)d_in[13];
    const float* out_w1 = (const float*)d_in[14];
    const float* out_b1 = (const float*)d_in[15];
    const float* out_w2 = (const float*)d_in[16];
    const float* out_b2 = (const float*)d_in[17];
    float* out = (float*)d_out;

    cudaFuncSetAttribute(k_edgeconv, cudaFuncAttributeMaxDynamicSharedMemorySize,
                         EC_SMEM_BYTES);
    cudaFuncSetAttribute(k_knn, cudaFuncAttributeMaxDynamicSharedMemorySize,
                         KNN_SMEM_BYTES);

    k_encoder<<<NN/256, 256>>>(x, enc_w1, enc_b1, enc_w2, enc_b2);
    k_knn<<<dim3(NM/128, NB), 128, KNN_SMEM_BYTES>>>(0);
    k_edgeconv<<<EC_GRID, 256, EC_SMEM_BYTES>>>(0, ec1_w1, ec1_b1, ec1_w2, ec1_b2);
    k_knn<<<dim3(NM/128, NB), 128, KNN_SMEM_BYTES>>>(1);
    k_edgeconv<<<EC_GRID, 256, EC_SMEM_BYTES>>>(1, ec2_w1, ec2_b1, ec2_w2, ec2_b2);
    k_final<<<NB, 256>>>(out_w1, out_b1, out_w2, out_b2, out);
}